// round 16
// baseline (speedup 1.0000x reference)
#include <cuda_runtime.h>
#include <cuda_fp16.h>
#include <cstdint>

// B=64, N=1000, D=512, H=8, S=20, DK=64
#define NEG_BIG (-1e9f)
#define INV_SQRT_DK 0.125f
#define INV_SQRT_D 0.04419417382415922f

// ---------------- device scratch ----------------
__device__ __align__(16) __half g_kvlh[64032 * 1536];     // [row][gk|gv|lk]; rows>=64000 stay zero
__device__ __align__(16) float g_logits[1280 * 1000];
__device__ __align__(16) __half g_Wkvl_t[1536 * 512];
__device__ __align__(16) __half g_Wout_t[512 * 512];
__device__ __align__(16) __half g_Hf16[1280 * 512];
__device__ __align__(16) __half g_Gf16[1280 * 512];
__device__ __align__(16) unsigned int g_mbits[1280 * 32];

// ---------------- helpers ----------------
__device__ __forceinline__ float warp_max(float v) {
#pragma unroll
    for (int o = 16; o; o >>= 1) v = fmaxf(v, __shfl_xor_sync(0xffffffffu, v, o));
    return v;
}
__device__ __forceinline__ float warp_sum(float v) {
#pragma unroll
    for (int o = 16; o; o >>= 1) v += __shfl_xor_sync(0xffffffffu, v, o);
    return v;
}
__device__ __forceinline__ uint32_t smem_u32(const void* p) {
    uint32_t a;
    asm("{ .reg .u64 t; cvta.to.shared.u64 t, %1; cvt.u32.u64 %0, t; }" : "=r"(a) : "l"(p));
    return a;
}
__device__ __forceinline__ void cp_async16(uint32_t saddr, const void* gaddr) {
    asm volatile("cp.async.cg.shared.global [%0], [%1], 16;" :: "r"(saddr), "l"(gaddr));
}
__device__ __forceinline__ void cp_commit() { asm volatile("cp.async.commit_group;" ::: "memory"); }
__device__ __forceinline__ void cp_wait1() { asm volatile("cp.async.wait_group 1;" ::: "memory"); }
__device__ __forceinline__ void cp_wait0() { asm volatile("cp.async.wait_group 0;" ::: "memory"); }

__device__ __forceinline__ void ldsm_x4(uint32_t& r0, uint32_t& r1, uint32_t& r2, uint32_t& r3,
                                        uint32_t addr) {
    asm volatile("ldmatrix.sync.aligned.m8n8.x4.shared.b16 {%0,%1,%2,%3}, [%4];"
                 : "=r"(r0), "=r"(r1), "=r"(r2), "=r"(r3) : "r"(addr));
}
__device__ __forceinline__ void ldsm_x4_t(uint32_t& r0, uint32_t& r1, uint32_t& r2, uint32_t& r3,
                                          uint32_t addr) {
    asm volatile("ldmatrix.sync.aligned.m8n8.x4.trans.shared.b16 {%0,%1,%2,%3}, [%4];"
                 : "=r"(r0), "=r"(r1), "=r"(r2), "=r"(r3) : "r"(addr));
}
__device__ __forceinline__ void mma16816(float& c0, float& c1, float& c2, float& c3,
                                         uint32_t a0, uint32_t a1, uint32_t a2, uint32_t a3,
                                         uint32_t b0, uint32_t b1) {
    asm volatile(
        "mma.sync.aligned.m16n8k16.row.col.f32.f16.f16.f32 "
        "{%0,%1,%2,%3}, {%4,%5,%6,%7}, {%8,%9}, {%0,%1,%2,%3};"
        : "+f"(c0), "+f"(c1), "+f"(c2), "+f"(c3)
        : "r"(a0), "r"(a1), "r"(a2), "r"(a3), "r"(b0), "r"(b1));
}

// ---------------- prep: W transposes + mask bits (emb conv now fused into GEMM) ----------------
// global bid: [0,3072) Wkvl^T; [3072,4096) Wout^T; [4096,5376) mask rows
__global__ __launch_bounds__(256)
void prep_kernel(const float* __restrict__ Wkvl, const float* __restrict__ Wout,
                 const unsigned int* __restrict__ mw, int boff)
{
    int bid = blockIdx.x + boff;
    int tid = threadIdx.x;
    if (bid < 3072) {
        int idx = bid * 256 + tid;
        int n = idx >> 9, k = idx & 511;
        g_Wkvl_t[idx] = __float2half_rn(Wkvl[(size_t)k * 1536 + n]);
    } else if (bid < 4096) {
        int idx = (bid - 3072) * 256 + tid;
        int n = idx >> 9, k = idx & 511;
        g_Wout_t[idx] = __float2half_rn(Wout[(size_t)k * 512 + n]);
    } else {
        __shared__ int flags;
        if (tid == 0) flags = 0;
        __syncthreads();
        int f = 0;
        for (int i = tid; i < 1024; i += 256) {
            unsigned int v = mw[i];
            if (v != 0u && v != 1u) f |= 1;
            if (v != 0u && v != 0x3F800000u) f |= 2;
        }
        if (f) atomicOr(&flags, f);
        __syncthreads();
        const int mode = ((flags & 1) && (flags & 2)) ? 0 : 1;
        const int lane = tid & 31, wid = tid >> 5;
        const int row = bid - 4096;
#pragma unroll
        for (int j = 0; j < 4; j++) {
            int widx = wid * 4 + j;
            int n = widx * 32 + lane;
            bool feas = false;
            if (n < 1000) {
                int idx = row * 1000 + n;
                feas = mode ? (mw[idx] != 0u)
                            : (((const unsigned char*)mw)[idx] != 0);
            }
            unsigned int word = __ballot_sync(0xffffffffu, feas);
            if (lane == 0) g_mbits[row * 32 + widx] = word;
        }
    }
}

// ---------------- BIG GEMM with fused fp32->fp16 A conversion ----------------
// C[M,Nn] = A(fp32)[M,512] @ Bt(fp16)[Nn,512]^T -> fp16.
// 128x128 tile, BK=64, 3-stage. A: LDG fp32 (pipelined 2 chunks ahead) + cvt + STS.
// B: cp.async. smem = 3 * 32768 = 98304.
__global__ __launch_bounds__(256)
void hmma_gemm_f32a(const float* __restrict__ A, const __half* __restrict__ Bt,
                    __half* __restrict__ C, int Nn)
{
    extern __shared__ char dsm[];
    const uint32_t sb = smem_u32(dsm);
    const int tid = threadIdx.x;
    const int bm = blockIdx.y * 128;
    const int bn = blockIdx.x * 128;
    const int lane = tid & 31, w = tid >> 5;
    const int wr = w >> 2;
    const int wc = w & 3;

    const float* Ag = A + (size_t)bm * 512;
    const char* Bg = (const char*)Bt + (size_t)bn * 1024;

    // per-thread A segments: 4 x (row, 8-half group). row = g>>3, ch = g&7.
    const int seg_row[1] = {0};
    (void)seg_row;

#define LDGA(kc, buf)                                                       \
    do {                                                                    \
        _Pragma("unroll")                                                   \
        for (int i_ = 0; i_ < 4; i_++) {                                    \
            int g_ = tid + i_ * 256;                                        \
            int row_ = g_ >> 3, ch_ = g_ & 7;                               \
            const float* src_ = Ag + (size_t)row_ * 512 + (kc) * 64 + ch_ * 8; \
            ar[buf][i_ * 2]     = *(const float4*)(src_);                   \
            ar[buf][i_ * 2 + 1] = *(const float4*)(src_ + 4);               \
        }                                                                   \
    } while (0)

#define STSA(kc, buf)                                                       \
    do {                                                                    \
        uint32_t st_ = sb + ((kc) % 3) * 32768;                             \
        _Pragma("unroll")                                                   \
        for (int i_ = 0; i_ < 4; i_++) {                                    \
            int g_ = tid + i_ * 256;                                        \
            int row_ = g_ >> 3, ch_ = g_ & 7;                               \
            uint32_t off_ = row_ * 128 + ch_ * 16;                          \
            uint32_t sw_ = off_ ^ ((off_ >> 3) & 0x70);                     \
            float4 v0_ = ar[buf][i_ * 2], v1_ = ar[buf][i_ * 2 + 1];        \
            __half2 h_[4];                                                  \
            h_[0] = __floats2half2_rn(v0_.x, v0_.y);                        \
            h_[1] = __floats2half2_rn(v0_.z, v0_.w);                        \
            h_[2] = __floats2half2_rn(v1_.x, v1_.y);                        \
            h_[3] = __floats2half2_rn(v1_.z, v1_.w);                        \
            *(uint4*)(dsm + (st_ - sb) + sw_) = *(uint4*)h_;                \
        }                                                                   \
    } while (0)

#define LDB(kc)                                                             \
    do {                                                                    \
        uint32_t st_ = sb + ((kc) % 3) * 32768;                             \
        size_t gk_ = (size_t)(kc) * 128;                                    \
        _Pragma("unroll")                                                   \
        for (int i_ = 0; i_ < 4; i_++) {                                    \
            int g_ = tid + i_ * 256;                                        \
            int row_ = g_ >> 3, ch_ = g_ & 7;                               \
            uint32_t off_ = row_ * 128 + ch_ * 16;                          \
            uint32_t sw_ = off_ ^ ((off_ >> 3) & 0x70);                     \
            cp_async16(st_ + 16384 + sw_, Bg + (size_t)row_ * 1024 + gk_ + ch_ * 16); \
        }                                                                   \
        cp_commit();                                                        \
    } while (0)

    float4 ar[2][8];
    float acc[4][4][4];
#pragma unroll
    for (int i = 0; i < 4; i++)
#pragma unroll
        for (int j = 0; j < 4; j++)
#pragma unroll
            for (int r = 0; r < 4; r++) acc[i][j][r] = 0.f;

    // prologue: A chunk0 -> regs -> smem; A chunk1 -> regs; B chunks 0,1 via cp.async
    LDGA(0, 0);
    STSA(0, 0);
    LDGA(1, 1);
    LDB(0);
    LDB(1);

    const int a_row = (lane & 15);
    const int a_c16 = (lane >> 4);
    const int b_nrow = (lane & 7) + ((lane >> 4) & 1) * 8;
    const int b_c16 = (lane >> 3) & 1;

    for (int kc = 0; kc < 8; ++kc) {
        if (kc == 7) cp_wait0(); else cp_wait1();
        __syncthreads();
        if (kc + 1 < 8) STSA(kc + 1, (kc + 1) & 1);      // data loaded last iter (or prologue)
        if (kc + 2 < 8) { LDGA(kc + 2, kc & 1); LDB(kc + 2); }

        uint32_t st = sb + (kc % 3) * 32768;
#pragma unroll
        for (int ks = 0; ks < 4; ++ks) {
            uint32_t af[4][4];
#pragma unroll
            for (int mi = 0; mi < 4; ++mi) {
                uint32_t off = (uint32_t)(wr * 64 + mi * 16 + a_row) * 128 + ks * 32 + a_c16 * 16;
                uint32_t sw = off ^ ((off >> 3) & 0x70);
                ldsm_x4(af[mi][0], af[mi][1], af[mi][2], af[mi][3], st + sw);
            }
            uint32_t bf[2][4];
#pragma unroll
            for (int pr = 0; pr < 2; ++pr) {
                uint32_t off = (uint32_t)(wc * 32 + pr * 16 + b_nrow) * 128 + ks * 32 + b_c16 * 16;
                uint32_t sw = off ^ ((off >> 3) & 0x70);
                ldsm_x4(bf[pr][0], bf[pr][1], bf[pr][2], bf[pr][3], st + 16384 + sw);
            }
#pragma unroll
            for (int mi = 0; mi < 4; ++mi) {
#pragma unroll
                for (int pr = 0; pr < 2; ++pr) {
                    mma16816(acc[mi][pr * 2][0], acc[mi][pr * 2][1],
                             acc[mi][pr * 2][2], acc[mi][pr * 2][3],
                             af[mi][0], af[mi][1], af[mi][2], af[mi][3],
                             bf[pr][0], bf[pr][1]);
                    mma16816(acc[mi][pr * 2 + 1][0], acc[mi][pr * 2 + 1][1],
                             acc[mi][pr * 2 + 1][2], acc[mi][pr * 2 + 1][3],
                             af[mi][0], af[mi][1], af[mi][2], af[mi][3],
                             bf[pr][2], bf[pr][3]);
                }
            }
        }
    }
    __syncthreads();

#pragma unroll
    for (int mi = 0; mi < 4; ++mi) {
        int row0 = bm + wr * 64 + mi * 16 + (lane >> 2);
#pragma unroll
        for (int ni = 0; ni < 4; ++ni) {
            int col = bn + wc * 32 + ni * 8 + (lane & 3) * 2;
            *(__half2*)(C + (size_t)row0 * Nn + col) =
                __floats2half2_rn(acc[mi][ni][0], acc[mi][ni][1]);
            *(__half2*)(C + (size_t)(row0 + 8) * Nn + col) =
                __floats2half2_rn(acc[mi][ni][2], acc[mi][ni][3]);
        }
    }
#undef LDGA
#undef STSA
#undef LDB
}

// ---------------- fp16 HMMA GEMM (glimpse): 128x128, 3-stage, fp16 out ----------------
__global__ __launch_bounds__(256, 2)
void hmma_gemm128(const __half* __restrict__ A, const __half* __restrict__ Bt,
                  __half* __restrict__ C, int Nn)
{
    extern __shared__ char dsm[];
    const uint32_t sb = smem_u32(dsm);
    const int tid = threadIdx.x;
    const int bm = blockIdx.y * 128;
    const int bn = blockIdx.x * 128;
    const int lane = tid & 31, w = tid >> 5;
    const int wr = w >> 2;
    const int wc = w & 3;

    const char* Ag = (const char*)A + (size_t)bm * 1024;
    const char* Bg = (const char*)Bt + (size_t)bn * 1024;

#define LOAD_CHUNK(kc)                                                      \
    do {                                                                    \
        uint32_t st_ = sb + ((kc) % 3) * 32768;                             \
        size_t gk_ = (size_t)(kc) * 128;                                    \
        _Pragma("unroll")                                                   \
        for (int i_ = 0; i_ < 4; i_++) {                                    \
            int g_ = tid + i_ * 256;                                        \
            int row_ = g_ >> 3, ch_ = g_ & 7;                               \
            uint32_t off_ = row_ * 128 + ch_ * 16;                          \
            uint32_t sw_ = off_ ^ ((off_ >> 3) & 0x70);                     \
            size_t go_ = (size_t)row_ * 1024 + gk_ + ch_ * 16;              \
            cp_async16(st_ + sw_, Ag + go_);                                \
            cp_async16(st_ + 16384 + sw_, Bg + go_);                        \
        }                                                                   \
        cp_commit();                                                        \
    } while (0)

    float acc[4][4][4];
#pragma unroll
    for (int i = 0; i < 4; i++)
#pragma unroll
        for (int j = 0; j < 4; j++)
#pragma unroll
            for (int r = 0; r < 4; r++) acc[i][j][r] = 0.f;

    LOAD_CHUNK(0);
    LOAD_CHUNK(1);

    const int a_row = (lane & 15);
    const int a_c16 = (lane >> 4);
    const int b_nrow = (lane & 7) + ((lane >> 4) & 1) * 8;
    const int b_c16 = (lane >> 3) & 1;

    for (int kc = 0; kc < 8; ++kc) {
        if (kc == 7) cp_wait0(); else cp_wait1();
        __syncthreads();
        if (kc + 2 < 8) LOAD_CHUNK(kc + 2);

        uint32_t st = sb + (kc % 3) * 32768;
#pragma unroll
        for (int ks = 0; ks < 4; ++ks) {
            uint32_t af[4][4];
#pragma unroll
            for (int mi = 0; mi < 4; ++mi) {
                uint32_t off = (uint32_t)(wr * 64 + mi * 16 + a_row) * 128 + ks * 32 + a_c16 * 16;
                uint32_t sw = off ^ ((off >> 3) & 0x70);
                ldsm_x4(af[mi][0], af[mi][1], af[mi][2], af[mi][3], st + sw);
            }
            uint32_t bf[2][4];
#pragma unroll
            for (int pr = 0; pr < 2; ++pr) {
                uint32_t off = (uint32_t)(wc * 32 + pr * 16 + b_nrow) * 128 + ks * 32 + b_c16 * 16;
                uint32_t sw = off ^ ((off >> 3) & 0x70);
                ldsm_x4(bf[pr][0], bf[pr][1], bf[pr][2], bf[pr][3], st + 16384 + sw);
            }
#pragma unroll
            for (int mi = 0; mi < 4; ++mi) {
#pragma unroll
                for (int pr = 0; pr < 2; ++pr) {
                    mma16816(acc[mi][pr * 2][0], acc[mi][pr * 2][1],
                             acc[mi][pr * 2][2], acc[mi][pr * 2][3],
                             af[mi][0], af[mi][1], af[mi][2], af[mi][3],
                             bf[pr][0], bf[pr][1]);
                    mma16816(acc[mi][pr * 2 + 1][0], acc[mi][pr * 2 + 1][1],
                             acc[mi][pr * 2 + 1][2], acc[mi][pr * 2 + 1][3],
                             af[mi][0], af[mi][1], af[mi][2], af[mi][3],
                             bf[pr][2], bf[pr][3]);
                }
            }
        }
    }
    __syncthreads();

#pragma unroll
    for (int mi = 0; mi < 4; ++mi) {
        int row0 = bm + wr * 64 + mi * 16 + (lane >> 2);
#pragma unroll
        for (int ni = 0; ni < 4; ++ni) {
            int col = bn + wc * 32 + ni * 8 + (lane & 3) * 2;
            *(__half2*)(C + (size_t)row0 * Nn + col) =
                __floats2half2_rn(acc[mi][ni][0], acc[mi][ni][1]);
            *(__half2*)(C + (size_t)(row0 + 8) * Nn + col) =
                __floats2half2_rn(acc[mi][ni][2], acc[mi][ni][3]);
        }
    }
#undef LOAD_CHUNK
}

// ---------------- tensor-core attention, exp-inline softmax, trans-ldmatrix V ----------------
#define ATT_P 0
#define ATT_KV 65536
#define ATT_Q 90112
#define ATT_MASK 94208
#define ATT_STAT 96768
#define ATT_SMEM 97024

__device__ __forceinline__ uint32_t psw(int row, int bytecol) {
    return (uint32_t)(row * 2048 + (bytecol ^ ((row & 7) << 4)));
}

__global__ __launch_bounds__(256)
void attn_mma_kernel(const float* __restrict__ qin)
{
    extern __shared__ char dsm[];
    const uint32_t sb = smem_u32(dsm);
    unsigned int* smask = (unsigned int*)(dsm + ATT_MASK);
    float* sl = (float*)(dsm + ATT_STAT);

    const int h = blockIdx.x, b = blockIdx.y;
    const int tid = threadIdx.x;
    const int lane = tid & 31, w = tid >> 5;
    const int wm = w >> 2, wn = w & 3;

    const int a_row = (lane & 15);
    const int a_c16 = (lane >> 4);
    const int b_nrow = (lane & 7) + ((lane >> 4) & 1) * 8;
    const int b_c16 = (lane >> 3) & 1;
    const int v_row = (lane & 7) + ((lane >> 3) & 1) * 8;
    const int v_c16 = lane >> 4;

    if (tid < 20) sl[tid] = 0.f;
    if (tid < 160) {
#pragma unroll
        for (int j = 0; j < 4; j++) {
            int idx = tid * 4 + j;
            smask[idx] = g_mbits[(b * 20 + (idx >> 5)) * 32 + (idx & 31)];
        }
    }
    for (int e = tid; e < 2048; e += 256) {
        int row = e >> 6, d = e & 63;
        __half v = __float2half_rn(0.f);
        if (row < 20) v = __float2half_rn(qin[((size_t)(b * 20 + row)) * 512 + h * 64 + d]);
        uint32_t off = (uint32_t)(row * 128 + d * 2);
        *(__half*)(dsm + ATT_Q + (off ^ ((off >> 3) & 0x70))) = v;
    }

#define LOADKV(t, voff)                                                       \
    do {                                                                      \
        uint32_t st_ = sb + ATT_KV + ((t) % 3) * 8192;                        \
        int n0_ = (t) * 64;                                                   \
        _Pragma("unroll")                                                     \
        for (int i_ = 0; i_ < 2; i_++) {                                      \
            int c_ = tid + i_ * 256;                                          \
            int row_ = c_ >> 3, j_ = c_ & 7;                                  \
            uint32_t off_ = row_ * 128 + j_ * 16;                             \
            uint32_t sw_ = off_ ^ ((off_ >> 3) & 0x70);                       \
            cp_async16(st_ + sw_,                                             \
                g_kvlh + ((size_t)b * 1000 + n0_ + row_) * 1536 + (voff) + h * 64 + j_ * 8); \
        }                                                                     \
        cp_commit();                                                          \
    } while (0)

    LOADKV(0, 0);
    LOADKV(1, 0);
    __syncthreads();

    uint32_t af[4][4];
#pragma unroll
    for (int ks = 0; ks < 4; ++ks) {
        uint32_t off = (uint32_t)((wm * 16 + a_row) * 128 + ks * 32 + a_c16 * 16);
        ldsm_x4(af[ks][0], af[ks][1], af[ks][2], af[ks][3],
                sb + ATT_Q + (off ^ ((off >> 3) & 0x70)));
    }

    const int r0 = wm * 16 + (lane >> 2);
    const int r1 = r0 + 8;
    float rsum0 = 0.f, rsum1 = 0.f;

    for (int t = 0; t < 16; ++t) {
        if (t >= 14) cp_wait0(); else cp_wait1();
        __syncthreads();
        if (t + 2 < 16) LOADKV(t + 2, 0);

        uint32_t st = sb + ATT_KV + (t % 3) * 8192;
        float acc[2][4] = {{0.f, 0.f, 0.f, 0.f}, {0.f, 0.f, 0.f, 0.f}};
#pragma unroll
        for (int ks = 0; ks < 4; ++ks) {
            uint32_t off = (uint32_t)((wn * 16 + b_nrow) * 128 + ks * 32 + b_c16 * 16);
            uint32_t bf0, bf1, bf2, bf3;
            ldsm_x4(bf0, bf1, bf2, bf3, st + (off ^ ((off >> 3) & 0x70)));
            mma16816(acc[0][0], acc[0][1], acc[0][2], acc[0][3],
                     af[ks][0], af[ks][1], af[ks][2], af[ks][3], bf0, bf1);
            mma16816(acc[1][0], acc[1][1], acc[1][2], acc[1][3],
                     af[ks][0], af[ks][1], af[ks][2], af[ks][3], bf2, bf3);
        }

        const int nb = t * 64 + wn * 16;
        const int widx = nb >> 5;
        unsigned int w0 = (r0 < 20) ? smask[r0 * 32 + widx] : 0u;
        unsigned int w1 = (r1 < 20) ? smask[r1 * 32 + widx] : 0u;
#pragma unroll
        for (int f = 0; f < 2; ++f) {
            int c = (lane & 3) * 2 + f * 8;
            int bit = (nb + c) & 31;
            float p00 = ((w0 >> bit) & 1u) ? fminf(__expf(acc[f][0] * INV_SQRT_DK), 60000.f) : 0.f;
            float p01 = ((w0 >> (bit + 1)) & 1u) ? fminf(__expf(acc[f][1] * INV_SQRT_DK), 60000.f) : 0.f;
            float p10 = ((w1 >> bit) & 1u) ? fminf(__expf(acc[f][2] * INV_SQRT_DK), 60000.f) : 0.f;
            float p11 = ((w1 >> (bit + 1)) & 1u) ? fminf(__expf(acc[f][3] * INV_SQRT_DK), 60000.f) : 0.f;
            rsum0 += p00 + p01;
            rsum1 += p10 + p11;
            int bytec = t * 128 + (wn * 16 + c) * 2;
            *(__half2*)(dsm + ATT_P + psw(r0, bytec)) = __floats2half2_rn(p00, p01);
            *(__half2*)(dsm + ATT_P + psw(r1, bytec)) = __floats2half2_rn(p10, p11);
        }
    }
    __syncthreads();

    LOADKV(0, 512);
    LOADKV(1, 512);

    rsum0 += __shfl_xor_sync(0xffffffffu, rsum0, 1);
    rsum0 += __shfl_xor_sync(0xffffffffu, rsum0, 2);
    rsum1 += __shfl_xor_sync(0xffffffffu, rsum1, 1);
    rsum1 += __shfl_xor_sync(0xffffffffu, rsum1, 2);
    if ((lane & 3) == 0) {
        if (r0 < 20) atomicAdd(&sl[r0], rsum0);
        if (r1 < 20) atomicAdd(&sl[r1], rsum1);
    }
    __syncthreads();

    float oacc[2][4] = {{0.f, 0.f, 0.f, 0.f}, {0.f, 0.f, 0.f, 0.f}};
    for (int t = 0; t < 16; ++t) {
        if (t >= 14) cp_wait0(); else cp_wait1();
        __syncthreads();
        if (t + 2 < 16) LOADKV(t + 2, 512);

        uint32_t st = sb + ATT_KV + (t % 3) * 8192;
#pragma unroll
        for (int ks = 0; ks < 4; ++ks) {
            uint32_t pa0, pa1, pa2, pa3;
            ldsm_x4(pa0, pa1, pa2, pa3,
                    sb + ATT_P + psw(wm * 16 + a_row, t * 128 + ks * 32 + a_c16 * 16));
            uint32_t off = (uint32_t)((ks * 16 + v_row) * 128 + wn * 32 + v_c16 * 16);
            uint32_t bf0, bf1, bf2, bf3;
            ldsm_x4_t(bf0, bf1, bf2, bf3, st + (off ^ ((off >> 3) & 0x70)));
            mma16816(oacc[0][0], oacc[0][1], oacc[0][2], oacc[0][3],
                     pa0, pa1, pa2, pa3, bf0, bf1);
            mma16816(oacc[1][0], oacc[1][1], oacc[1][2], oacc[1][3],
                     pa0, pa1, pa2, pa3, bf2, bf3);
        }
    }

#pragma unroll
    for (int f = 0; f < 2; ++f) {
        int col = h * 64 + wn * 16 + f * 8 + (lane & 3) * 2;
        if (r0 < 20) {
            float inv = 1.f / sl[r0];
            *(__half2*)(g_Hf16 + ((size_t)(b * 20 + r0)) * 512 + col) =
                __floats2half2_rn(oacc[f][0] * inv, oacc[f][1] * inv);
        }
        if (r1 < 20) {
            float inv = 1.f / sl[r1];
            *(__half2*)(g_Hf16 + ((size_t)(b * 20 + r1)) * 512 + col) =
                __floats2half2_rn(oacc[f][2] * inv, oacc[f][3] * inv);
        }
    }
#undef LOADKV
}

// ---------------- pointer logits via MMA ----------------
#define PTR_A 0
#define PTR_B 32768
#define PTR_MASK 49152
#define PTR_SMEM 51712

__global__ __launch_bounds__(256)
void pointer_mma_kernel()
{
    extern __shared__ char dsm[];
    const uint32_t sb = smem_u32(dsm);
    unsigned int* smask = (unsigned int*)(dsm + PTR_MASK);

    const int nsl = blockIdx.x, b = blockIdx.y;
    const int tid = threadIdx.x;
    const int lane = tid & 31, w = tid >> 5;
    const int wm = w >> 2, wn = w & 3;

    const int a_row = (lane & 15);
    const int a_c16 = (lane >> 4);
    const int b_nrow = (lane & 7) + ((lane >> 4) & 1) * 8;
    const int b_c16 = (lane >> 3) & 1;

    for (int i = tid; i < 32768 / 16; i += 256)
        *(uint4*)(dsm + PTR_A + i * 16) = make_uint4(0u, 0u, 0u, 0u);
    if (tid < 160) {
#pragma unroll
        for (int j = 0; j < 4; j++) {
            int idx = tid * 4 + j;
            smask[idx] = g_mbits[(b * 20 + (idx >> 5)) * 32 + (idx & 31)];
        }
    }
    __syncthreads();

    for (int c = tid; c < 20 * 64; c += 256) {
        int row = c >> 6, j = c & 63;
        int kc = j >> 3, jj = j & 7;
        uint32_t off = (uint32_t)(row * 128 + jj * 16);
        uint32_t sw = off ^ ((off >> 3) & 0x70);
        *(uint4*)(dsm + PTR_A + kc * 4096 + sw) =
            *(const uint4*)(g_Gf16 + ((size_t)(b * 20 + row)) * 512 + kc * 64 + jj * 8);
    }

#define PLOADB(step)                                                          \
    do {                                                                      \
        int nt_ = (step) >> 3, kc_ = (step) & 7;                              \
        uint32_t st_ = sb + PTR_B + ((step) & 1) * 8192;                      \
        _Pragma("unroll")                                                     \
        for (int i_ = 0; i_ < 2; i_++) {                                      \
            int c_ = tid + i_ * 256;                                          \
            int row_ = c_ >> 3, j_ = c_ & 7;                                  \
            uint32_t off_ = row_ * 128 + j_ * 16;                             \
            uint32_t sw_ = off_ ^ ((off_ >> 3) & 0x70);                       \
            cp_async16(st_ + sw_,                                             \
                g_kvlh + ((size_t)b * 1000 + nsl * 512 + nt_ * 64 + row_) * 1536 + 1024 + kc_ * 64 + j_ * 8); \
        }                                                                     \
        cp_commit();                                                          \
    } while (0)

    PLOADB(0);
    __syncthreads();

    const int r0 = wm * 16 + (lane >> 2);
    const int r1 = r0 + 8;

    float acc[2][4];
    for (int step = 0; step < 64; ++step) {
        if (step + 1 < 64) { PLOADB(step + 1); cp_wait1(); } else { cp_wait0(); }
        __syncthreads();

        const int kc = step & 7;
        if (kc == 0) {
#pragma unroll
            for (int f = 0; f < 2; ++f)
#pragma unroll
                for (int r = 0; r < 4; ++r) acc[f][r] = 0.f;
        }

        uint32_t stB = sb + PTR_B + (step & 1) * 8192;
#pragma unroll
        for (int ks = 0; ks < 4; ++ks) {
            uint32_t a0, a1, a2, a3;
            uint32_t offA = (uint32_t)((wm * 16 + a_row) * 128 + ks * 32 + a_c16 * 16);
            ldsm_x4(a0, a1, a2, a3, sb + PTR_A + kc * 4096 + (offA ^ ((offA >> 3) & 0x70)));
            uint32_t offB = (uint32_t)((wn * 16 + b_nrow) * 128 + ks * 32 + b_c16 * 16);
            uint32_t bf0, bf1, bf2, bf3;
            ldsm_x4(bf0, bf1, bf2, bf3, stB + (offB ^ ((offB >> 3) & 0x70)));
            mma16816(acc[0][0], acc[0][1], acc[0][2], acc[0][3], a0, a1, a2, a3, bf0, bf1);
            mma16816(acc[1][0], acc[1][1], acc[1][2], acc[1][3], a0, a1, a2, a3, bf2, bf3);
        }

        if (kc == 7) {
            const int nt = step >> 3;
            const int nb = nsl * 512 + nt * 64 + wn * 16;
            const int widx = nb >> 5;
            unsigned int w0 = (r0 < 20) ? smask[r0 * 32 + widx] : 0u;
            unsigned int w1 = (r1 < 20) ? smask[r1 * 32 + widx] : 0u;
#pragma unroll
            for (int f = 0; f < 2; ++f) {
                int c = (lane & 3) * 2 + f * 8;
                int gn = nb + c;
                int bit = gn & 31;
                if (r0 < 20) {
                    if (gn < 1000) {
                        float lg = ((w0 >> bit) & 1u)
                                 ? 10.f * tanhf(acc[f][0] * INV_SQRT_D) : NEG_BIG;
                        g_logits[(size_t)(b * 20 + r0) * 1000 + gn] = lg;
                    }
                    if (gn + 1 < 1000) {
                        float lg = ((w0 >> (bit + 1)) & 1u)
                                 ? 10.f * tanhf(acc[f][1] * INV_SQRT_D) : NEG_BIG;
                        g_logits[(size_t)(b * 20 + r0) * 1000 + gn + 1] = lg;
                    }
                }
                if (r1 < 20) {
                    if (gn < 1000) {
                        float lg = ((w1 >> bit) & 1u)
                                 ? 10.f * tanhf(acc[f][2] * INV_SQRT_D) : NEG_BIG;
                        g_logits[(size_t)(b * 20 + r1) * 1000 + gn] = lg;
                    }
                    if (gn + 1 < 1000) {
                        float lg = ((w1 >> (bit + 1)) & 1u)
                                 ? 10.f * tanhf(acc[f][3] * INV_SQRT_D) : NEG_BIG;
                        g_logits[(size_t)(b * 20 + r1) * 1000 + gn + 1] = lg;
                    }
                }
            }
        }
        __syncthreads();
    }
#undef PLOADB
}

// ---------------- log-softmax + transposed writeout ----------------
__global__ __launch_bounds__(256)
void lsm_kernel(float* __restrict__ out)
{
    const int s = blockIdx.x, b = blockIdx.y;
    const float* row = g_logits + (size_t)(b * 20 + s) * 1000;
    float* orow = out + (size_t)(s * 64 + b) * 1000;
    __shared__ float red[8];
    const int tid = threadIdx.x;
    const int lane = tid & 31, w = tid >> 5;

    float mx = -1e30f;
    for (int i = tid; i < 1000; i += 256) mx = fmaxf(mx, row[i]);
    mx = warp_max(mx);
    if (lane == 0) red[w] = mx;
    __syncthreads();
    if (w == 0) {
        float v = (lane < 8) ? red[lane] : -1e30f;
        v = warp_max(v);
        if (lane == 0) red[0] = v;
    }
    __syncthreads();
    mx = red[0];
    __syncthreads();

    float se = 0.f;
    for (int i = tid; i < 1000; i += 256) se += __expf(row[i] - mx);
    se = warp_sum(se);
    if (lane == 0) red[w] = se;
    __syncthreads();
    if (w == 0) {
        float v = (lane < 8) ? red[lane] : 0.f;
        v = warp_sum(v);
        if (lane == 0) red[0] = v;
    }
    __syncthreads();
    const float lse = mx + logf(red[0]);

    for (int i = tid; i < 1000; i += 256) orow[i] = row[i] - lse;
}

// ---------------- launch ----------------
extern "C" void kernel_launch(void* const* d_in, const int* in_sizes, int n_in,
                              void* d_out, int out_size)
{
    (void)out_size;
    const float* emb = nullptr;
    const float* q = nullptr;
    const void* mask = nullptr;
    const float* Wkvl = nullptr;
    const float* Wout = nullptr;
    for (int i = 0; i < n_in; ++i) {
        switch (in_sizes[i]) {
            case 32768000: emb = (const float*)d_in[i]; break;
            case 655360:   q = (const float*)d_in[i]; break;
            case 1280000:  mask = d_in[i]; break;
            case 786432:   Wkvl = (const float*)d_in[i]; break;
            case 262144:   Wout = (const float*)d_in[i]; break;
            default: break;
        }
    }
    float* out = (float*)d_out;

    __half *kvlhp, *wkt, *wot, *hf16, *gf16;
    cudaGetSymbolAddress((void**)&kvlhp, g_kvlh);
    cudaGetSymbolAddress((void**)&wkt, g_Wkvl_t);
    cudaGetSymbolAddress((void**)&wot, g_Wout_t);
    cudaGetSymbolAddress((void**)&hf16, g_Hf16);
    cudaGetSymbolAddress((void**)&gf16, g_Gf16);

    cudaFuncSetAttribute(hmma_gemm_f32a, cudaFuncAttributeMaxDynamicSharedMemorySize, 98304);
    cudaFuncSetAttribute(hmma_gemm128, cudaFuncAttributeMaxDynamicSharedMemorySize, 98304);
    cudaFuncSetAttribute(attn_mma_kernel, cudaFuncAttributeMaxDynamicSharedMemorySize, ATT_SMEM);
    cudaFuncSetAttribute(pointer_mma_kernel, cudaFuncAttributeMaxDynamicSharedMemorySize, PTR_SMEM);

    const unsigned int* mw = (const unsigned int*)mask;
    // 1-3: prep (small) split so the big GEMM is profiled slot #4
    prep_kernel<<<3072, 256>>>(Wkvl, Wout, mw, 0);
    prep_kernel<<<1024, 256>>>(Wkvl, Wout, mw, 3072);
    prep_kernel<<<1280, 256>>>(Wkvl, Wout, mw, 4096);

    // 4: kvl = emb(fp32) @ W_kvl -> g_kvlh, conversion fused (profiled)
    {
        dim3 grid(12, 500);
        hmma_gemm_f32a<<<grid, 256, 98304>>>(emb, wkt, kvlhp, 1536);
    }

    // 5: tensor-core attention
    {
        dim3 grid(8, 64);
        attn_mma_kernel<<<grid, 256, ATT_SMEM>>>(q);
    }

    // 6: glimpse = heads @ W_out -> fp16
    {
        dim3 grid(4, 10);
        hmma_gemm128<<<grid, 256, 98304>>>(hf16, wot, gf16, 512);
    }

    // 7: pointer logits via MMA
    {
        dim3 grid(2, 64);
        pointer_mma_kernel<<<grid, 256, PTR_SMEM>>>();
    }

    // 8: log-softmax
    {
        dim3 grid(20, 64);
        lsm_kernel<<<grid, 256>>>(out);
    }
}

// round 17
// speedup vs baseline: 1.7908x; 1.7908x over previous
#include <cuda_runtime.h>
#include <cuda_fp16.h>
#include <cstdint>

// B=64, N=1000, D=512, H=8, S=20, DK=64
#define NEG_BIG (-1e9f)
#define INV_SQRT_DK 0.125f
#define INV_SQRT_D 0.04419417382415922f

// ---------------- device scratch ----------------
__device__ __align__(16) __half g_kvlh[64032 * 1536];     // [row][gk|gv|lk]; rows>=64000 stay zero
__device__ __align__(16) float g_logits[1280 * 1000];
__device__ __align__(16) __half g_Af16[64000 * 512];
__device__ __align__(16) __half g_Wkvl_t[1536 * 512];
__device__ __align__(16) __half g_Wout_t[512 * 512];
__device__ __align__(16) __half g_Hf16[1280 * 512];
__device__ __align__(16) __half g_Gf16[1280 * 512];
__device__ __align__(16) unsigned int g_mbits[1280 * 32];

// ---------------- helpers ----------------
__device__ __forceinline__ float warp_max(float v) {
#pragma unroll
    for (int o = 16; o; o >>= 1) v = fmaxf(v, __shfl_xor_sync(0xffffffffu, v, o));
    return v;
}
__device__ __forceinline__ float warp_sum(float v) {
#pragma unroll
    for (int o = 16; o; o >>= 1) v += __shfl_xor_sync(0xffffffffu, v, o);
    return v;
}
__device__ __forceinline__ uint32_t smem_u32(const void* p) {
    uint32_t a;
    asm("{ .reg .u64 t; cvta.to.shared.u64 t, %1; cvt.u32.u64 %0, t; }" : "=r"(a) : "l"(p));
    return a;
}
__device__ __forceinline__ void cp_async16(uint32_t saddr, const void* gaddr) {
    asm volatile("cp.async.cg.shared.global [%0], [%1], 16;" :: "r"(saddr), "l"(gaddr));
}
__device__ __forceinline__ void cp_commit() { asm volatile("cp.async.commit_group;" ::: "memory"); }
__device__ __forceinline__ void cp_wait1() { asm volatile("cp.async.wait_group 1;" ::: "memory"); }
__device__ __forceinline__ void cp_wait0() { asm volatile("cp.async.wait_group 0;" ::: "memory"); }

__device__ __forceinline__ void ldsm_x4(uint32_t& r0, uint32_t& r1, uint32_t& r2, uint32_t& r3,
                                        uint32_t addr) {
    asm volatile("ldmatrix.sync.aligned.m8n8.x4.shared.b16 {%0,%1,%2,%3}, [%4];"
                 : "=r"(r0), "=r"(r1), "=r"(r2), "=r"(r3) : "r"(addr));
}
__device__ __forceinline__ void ldsm_x4_t(uint32_t& r0, uint32_t& r1, uint32_t& r2, uint32_t& r3,
                                          uint32_t addr) {
    asm volatile("ldmatrix.sync.aligned.m8n8.x4.trans.shared.b16 {%0,%1,%2,%3}, [%4];"
                 : "=r"(r0), "=r"(r1), "=r"(r2), "=r"(r3) : "r"(addr));
}
__device__ __forceinline__ void mma16816(float& c0, float& c1, float& c2, float& c3,
                                         uint32_t a0, uint32_t a1, uint32_t a2, uint32_t a3,
                                         uint32_t b0, uint32_t b1) {
    asm volatile(
        "mma.sync.aligned.m16n8k16.row.col.f32.f16.f16.f32 "
        "{%0,%1,%2,%3}, {%4,%5,%6,%7}, {%8,%9}, {%0,%1,%2,%3};"
        : "+f"(c0), "+f"(c1), "+f"(c2), "+f"(c3)
        : "r"(a0), "r"(a1), "r"(a2), "r"(a3), "r"(b0), "r"(b1));
}

// ---------------- fused prep: emb->fp16, W transposes, mask bits (one launch) ----------------
// bid: [0,32000) emb; [32000,35072) Wkvl^T; [35072,36096) Wout^T; [36096,37376) mask rows
__global__ __launch_bounds__(256)
void prep_kernel(const float* __restrict__ emb, const float* __restrict__ Wkvl,
                 const float* __restrict__ Wout, const unsigned int* __restrict__ mw)
{
    int bid = blockIdx.x;
    int tid = threadIdx.x;
    if (bid < 32000) {
        int i = bid * 256 + tid;
        float4 v = ((const float4*)emb)[i];
        ((__half2*)g_Af16)[i * 2] = __floats2half2_rn(v.x, v.y);
        ((__half2*)g_Af16)[i * 2 + 1] = __floats2half2_rn(v.z, v.w);
    } else if (bid < 35072) {
        int idx = (bid - 32000) * 256 + tid;
        int n = idx >> 9, k = idx & 511;
        g_Wkvl_t[idx] = __float2half_rn(Wkvl[(size_t)k * 1536 + n]);
    } else if (bid < 36096) {
        int idx = (bid - 35072) * 256 + tid;
        int n = idx >> 9, k = idx & 511;
        g_Wout_t[idx] = __float2half_rn(Wout[(size_t)k * 512 + n]);
    } else {
        __shared__ int flags;
        if (tid == 0) flags = 0;
        __syncthreads();
        int f = 0;
        for (int i = tid; i < 1024; i += 256) {
            unsigned int v = mw[i];
            if (v != 0u && v != 1u) f |= 1;
            if (v != 0u && v != 0x3F800000u) f |= 2;
        }
        if (f) atomicOr(&flags, f);
        __syncthreads();
        const int mode = ((flags & 1) && (flags & 2)) ? 0 : 1;
        const int lane = tid & 31, wid = tid >> 5;
        const int row = bid - 36096;
#pragma unroll
        for (int j = 0; j < 4; j++) {
            int widx = wid * 4 + j;
            int n = widx * 32 + lane;
            bool feas = false;
            if (n < 1000) {
                int idx = row * 1000 + n;
                feas = mode ? (mw[idx] != 0u)
                            : (((const unsigned char*)mw)[idx] != 0);
            }
            unsigned int word = __ballot_sync(0xffffffffu, feas);
            if (lane == 0) g_mbits[row * 32 + widx] = word;
        }
    }
}

// ---------------- fp16 HMMA GEMM: 128x128 tile, 256 threads, 3-stage, 2 CTAs/SM ----------------
__global__ __launch_bounds__(256, 2)
void hmma_gemm128(const __half* __restrict__ A, const __half* __restrict__ Bt,
                  __half* __restrict__ C, int Nn)
{
    extern __shared__ char dsm[];
    const uint32_t sb = smem_u32(dsm);
    const int tid = threadIdx.x;
    const int bm = blockIdx.y * 128;
    const int bn = blockIdx.x * 128;
    const int lane = tid & 31, w = tid >> 5;
    const int wr = w >> 2;
    const int wc = w & 3;

    const char* Ag = (const char*)A + (size_t)bm * 1024;
    const char* Bg = (const char*)Bt + (size_t)bn * 1024;

#define LOAD_CHUNK(kc)                                                      \
    do {                                                                    \
        uint32_t st_ = sb + ((kc) % 3) * 32768;                             \
        size_t gk_ = (size_t)(kc) * 128;                                    \
        _Pragma("unroll")                                                   \
        for (int i_ = 0; i_ < 4; i_++) {                                    \
            int g_ = tid + i_ * 256;                                        \
            int row_ = g_ >> 3, ch_ = g_ & 7;                               \
            uint32_t off_ = row_ * 128 + ch_ * 16;                          \
            uint32_t sw_ = off_ ^ ((off_ >> 3) & 0x70);                     \
            size_t go_ = (size_t)row_ * 1024 + gk_ + ch_ * 16;              \
            cp_async16(st_ + sw_, Ag + go_);                                \
            cp_async16(st_ + 16384 + sw_, Bg + go_);                        \
        }                                                                   \
        cp_commit();                                                        \
    } while (0)

    float acc[4][4][4];
#pragma unroll
    for (int i = 0; i < 4; i++)
#pragma unroll
        for (int j = 0; j < 4; j++)
#pragma unroll
            for (int r = 0; r < 4; r++) acc[i][j][r] = 0.f;

    LOAD_CHUNK(0);
    LOAD_CHUNK(1);

    const int a_row = (lane & 15);
    const int a_c16 = (lane >> 4);
    const int b_nrow = (lane & 7) + ((lane >> 4) & 1) * 8;
    const int b_c16 = (lane >> 3) & 1;

    for (int kc = 0; kc < 8; ++kc) {
        if (kc == 7) cp_wait0(); else cp_wait1();
        __syncthreads();
        if (kc + 2 < 8) LOAD_CHUNK(kc + 2);

        uint32_t st = sb + (kc % 3) * 32768;
#pragma unroll
        for (int ks = 0; ks < 4; ++ks) {
            uint32_t af[4][4];
#pragma unroll
            for (int mi = 0; mi < 4; ++mi) {
                uint32_t off = (uint32_t)(wr * 64 + mi * 16 + a_row) * 128 + ks * 32 + a_c16 * 16;
                uint32_t sw = off ^ ((off >> 3) & 0x70);
                ldsm_x4(af[mi][0], af[mi][1], af[mi][2], af[mi][3], st + sw);
            }
            uint32_t bf[2][4];
#pragma unroll
            for (int pr = 0; pr < 2; ++pr) {
                uint32_t off = (uint32_t)(wc * 32 + pr * 16 + b_nrow) * 128 + ks * 32 + b_c16 * 16;
                uint32_t sw = off ^ ((off >> 3) & 0x70);
                ldsm_x4(bf[pr][0], bf[pr][1], bf[pr][2], bf[pr][3], st + 16384 + sw);
            }
#pragma unroll
            for (int mi = 0; mi < 4; ++mi) {
#pragma unroll
                for (int pr = 0; pr < 2; ++pr) {
                    mma16816(acc[mi][pr * 2][0], acc[mi][pr * 2][1],
                             acc[mi][pr * 2][2], acc[mi][pr * 2][3],
                             af[mi][0], af[mi][1], af[mi][2], af[mi][3],
                             bf[pr][0], bf[pr][1]);
                    mma16816(acc[mi][pr * 2 + 1][0], acc[mi][pr * 2 + 1][1],
                             acc[mi][pr * 2 + 1][2], acc[mi][pr * 2 + 1][3],
                             af[mi][0], af[mi][1], af[mi][2], af[mi][3],
                             bf[pr][2], bf[pr][3]);
                }
            }
        }
    }
    __syncthreads();

#pragma unroll
    for (int mi = 0; mi < 4; ++mi) {
        int row0 = bm + wr * 64 + mi * 16 + (lane >> 2);
#pragma unroll
        for (int ni = 0; ni < 4; ++ni) {
            int col = bn + wc * 32 + ni * 8 + (lane & 3) * 2;
            *(__half2*)(C + (size_t)row0 * Nn + col) =
                __floats2half2_rn(acc[mi][ni][0], acc[mi][ni][1]);
            *(__half2*)(C + (size_t)(row0 + 8) * Nn + col) =
                __floats2half2_rn(acc[mi][ni][2], acc[mi][ni][3]);
        }
    }
#undef LOAD_CHUNK
}

// ---------------- tensor-core attention, exp-inline softmax, trans-ldmatrix V ----------------
#define ATT_P 0
#define ATT_KV 65536
#define ATT_Q 90112
#define ATT_MASK 94208
#define ATT_STAT 96768
#define ATT_SMEM 97024

__device__ __forceinline__ uint32_t psw(int row, int bytecol) {
    return (uint32_t)(row * 2048 + (bytecol ^ ((row & 7) << 4)));
}

__global__ __launch_bounds__(256, 2)
void attn_mma_kernel(const float* __restrict__ qin)
{
    extern __shared__ char dsm[];
    const uint32_t sb = smem_u32(dsm);
    unsigned int* smask = (unsigned int*)(dsm + ATT_MASK);
    float* sl = (float*)(dsm + ATT_STAT);

    const int h = blockIdx.x, b = blockIdx.y;
    const int tid = threadIdx.x;
    const int lane = tid & 31, w = tid >> 5;
    const int wm = w >> 2, wn = w & 3;

    const int a_row = (lane & 15);
    const int a_c16 = (lane >> 4);
    const int b_nrow = (lane & 7) + ((lane >> 4) & 1) * 8;
    const int b_c16 = (lane >> 3) & 1;
    const int v_row = (lane & 7) + ((lane >> 3) & 1) * 8;
    const int v_c16 = lane >> 4;

    if (tid < 20) sl[tid] = 0.f;
    if (tid < 160) {
#pragma unroll
        for (int j = 0; j < 4; j++) {
            int idx = tid * 4 + j;
            smask[idx] = g_mbits[(b * 20 + (idx >> 5)) * 32 + (idx & 31)];
        }
    }
    for (int e = tid; e < 2048; e += 256) {
        int row = e >> 6, d = e & 63;
        __half v = __float2half_rn(0.f);
        if (row < 20) v = __float2half_rn(qin[((size_t)(b * 20 + row)) * 512 + h * 64 + d]);
        uint32_t off = (uint32_t)(row * 128 + d * 2);
        *(__half*)(dsm + ATT_Q + (off ^ ((off >> 3) & 0x70))) = v;
    }

#define LOADKV(t, voff)                                                       \
    do {                                                                      \
        uint32_t st_ = sb + ATT_KV + ((t) % 3) * 8192;                        \
        int n0_ = (t) * 64;                                                   \
        _Pragma("unroll")                                                     \
        for (int i_ = 0; i_ < 2; i_++) {                                      \
            int c_ = tid + i_ * 256;                                          \
            int row_ = c_ >> 3, j_ = c_ & 7;                                  \
            uint32_t off_ = row_ * 128 + j_ * 16;                             \
            uint32_t sw_ = off_ ^ ((off_ >> 3) & 0x70);                       \
            cp_async16(st_ + sw_,                                             \
                g_kvlh + ((size_t)b * 1000 + n0_ + row_) * 1536 + (voff) + h * 64 + j_ * 8); \
        }                                                                     \
        cp_commit();                                                          \
    } while (0)

    LOADKV(0, 0);
    LOADKV(1, 0);
    __syncthreads();

    uint32_t af[4][4];
#pragma unroll
    for (int ks = 0; ks < 4; ++ks) {
        uint32_t off = (uint32_t)((wm * 16 + a_row) * 128 + ks * 32 + a_c16 * 16);
        ldsm_x4(af[ks][0], af[ks][1], af[ks][2], af[ks][3],
                sb + ATT_Q + (off ^ ((off >> 3) & 0x70)));
    }

    const int r0 = wm * 16 + (lane >> 2);
    const int r1 = r0 + 8;
    float rsum0 = 0.f, rsum1 = 0.f;

    for (int t = 0; t < 16; ++t) {
        if (t >= 14) cp_wait0(); else cp_wait1();
        __syncthreads();
        if (t + 2 < 16) LOADKV(t + 2, 0);

        uint32_t st = sb + ATT_KV + (t % 3) * 8192;
        float acc[2][4] = {{0.f, 0.f, 0.f, 0.f}, {0.f, 0.f, 0.f, 0.f}};
#pragma unroll
        for (int ks = 0; ks < 4; ++ks) {
            uint32_t off = (uint32_t)((wn * 16 + b_nrow) * 128 + ks * 32 + b_c16 * 16);
            uint32_t bf0, bf1, bf2, bf3;
            ldsm_x4(bf0, bf1, bf2, bf3, st + (off ^ ((off >> 3) & 0x70)));
            mma16816(acc[0][0], acc[0][1], acc[0][2], acc[0][3],
                     af[ks][0], af[ks][1], af[ks][2], af[ks][3], bf0, bf1);
            mma16816(acc[1][0], acc[1][1], acc[1][2], acc[1][3],
                     af[ks][0], af[ks][1], af[ks][2], af[ks][3], bf2, bf3);
        }

        const int nb = t * 64 + wn * 16;
        const int widx = nb >> 5;
        unsigned int w0 = (r0 < 20) ? smask[r0 * 32 + widx] : 0u;
        unsigned int w1 = (r1 < 20) ? smask[r1 * 32 + widx] : 0u;
#pragma unroll
        for (int f = 0; f < 2; ++f) {
            int c = (lane & 3) * 2 + f * 8;
            int bit = (nb + c) & 31;
            float p00 = ((w0 >> bit) & 1u) ? fminf(__expf(acc[f][0] * INV_SQRT_DK), 60000.f) : 0.f;
            float p01 = ((w0 >> (bit + 1)) & 1u) ? fminf(__expf(acc[f][1] * INV_SQRT_DK), 60000.f) : 0.f;
            float p10 = ((w1 >> bit) & 1u) ? fminf(__expf(acc[f][2] * INV_SQRT_DK), 60000.f) : 0.f;
            float p11 = ((w1 >> (bit + 1)) & 1u) ? fminf(__expf(acc[f][3] * INV_SQRT_DK), 60000.f) : 0.f;
            rsum0 += p00 + p01;
            rsum1 += p10 + p11;
            int bytec = t * 128 + (wn * 16 + c) * 2;
            *(__half2*)(dsm + ATT_P + psw(r0, bytec)) = __floats2half2_rn(p00, p01);
            *(__half2*)(dsm + ATT_P + psw(r1, bytec)) = __floats2half2_rn(p10, p11);
        }
    }
    __syncthreads();

    LOADKV(0, 512);
    LOADKV(1, 512);

    rsum0 += __shfl_xor_sync(0xffffffffu, rsum0, 1);
    rsum0 += __shfl_xor_sync(0xffffffffu, rsum0, 2);
    rsum1 += __shfl_xor_sync(0xffffffffu, rsum1, 1);
    rsum1 += __shfl_xor_sync(0xffffffffu, rsum1, 2);
    if ((lane & 3) == 0) {
        if (r0 < 20) atomicAdd(&sl[r0], rsum0);
        if (r1 < 20) atomicAdd(&sl[r1], rsum1);
    }
    __syncthreads();

    float oacc[2][4] = {{0.f, 0.f, 0.f, 0.f}, {0.f, 0.f, 0.f, 0.f}};
    for (int t = 0; t < 16; ++t) {
        if (t >= 14) cp_wait0(); else cp_wait1();
        __syncthreads();
        if (t + 2 < 16) LOADKV(t + 2, 512);

        uint32_t st = sb + ATT_KV + (t % 3) * 8192;
#pragma unroll
        for (int ks = 0; ks < 4; ++ks) {
            uint32_t pa0, pa1, pa2, pa3;
            ldsm_x4(pa0, pa1, pa2, pa3,
                    sb + ATT_P + psw(wm * 16 + a_row, t * 128 + ks * 32 + a_c16 * 16));
            uint32_t off = (uint32_t)((ks * 16 + v_row) * 128 + wn * 32 + v_c16 * 16);
            uint32_t bf0, bf1, bf2, bf3;
            ldsm_x4_t(bf0, bf1, bf2, bf3, st + (off ^ ((off >> 3) & 0x70)));
            mma16816(oacc[0][0], oacc[0][1], oacc[0][2], oacc[0][3],
                     pa0, pa1, pa2, pa3, bf0, bf1);
            mma16816(oacc[1][0], oacc[1][1], oacc[1][2], oacc[1][3],
                     pa0, pa1, pa2, pa3, bf2, bf3);
        }
    }

#pragma unroll
    for (int f = 0; f < 2; ++f) {
        int col = h * 64 + wn * 16 + f * 8 + (lane & 3) * 2;
        if (r0 < 20) {
            float inv = 1.f / sl[r0];
            *(__half2*)(g_Hf16 + ((size_t)(b * 20 + r0)) * 512 + col) =
                __floats2half2_rn(oacc[f][0] * inv, oacc[f][1] * inv);
        }
        if (r1 < 20) {
            float inv = 1.f / sl[r1];
            *(__half2*)(g_Hf16 + ((size_t)(b * 20 + r1)) * 512 + col) =
                __floats2half2_rn(oacc[f][2] * inv, oacc[f][3] * inv);
        }
    }
#undef LOADKV
}

// ---------------- pointer logits via MMA ----------------
#define PTR_A 0
#define PTR_B 32768
#define PTR_MASK 49152
#define PTR_SMEM 51712

__global__ __launch_bounds__(256)
void pointer_mma_kernel()
{
    extern __shared__ char dsm[];
    const uint32_t sb = smem_u32(dsm);
    unsigned int* smask = (unsigned int*)(dsm + PTR_MASK);

    const int nsl = blockIdx.x, b = blockIdx.y;
    const int tid = threadIdx.x;
    const int lane = tid & 31, w = tid >> 5;
    const int wm = w >> 2, wn = w & 3;

    const int a_row = (lane & 15);
    const int a_c16 = (lane >> 4);
    const int b_nrow = (lane & 7) + ((lane >> 4) & 1) * 8;
    const int b_c16 = (lane >> 3) & 1;

    for (int i = tid; i < 32768 / 16; i += 256)
        *(uint4*)(dsm + PTR_A + i * 16) = make_uint4(0u, 0u, 0u, 0u);
    if (tid < 160) {
#pragma unroll
        for (int j = 0; j < 4; j++) {
            int idx = tid * 4 + j;
            smask[idx] = g_mbits[(b * 20 + (idx >> 5)) * 32 + (idx & 31)];
        }
    }
    __syncthreads();

    for (int c = tid; c < 20 * 64; c += 256) {
        int row = c >> 6, j = c & 63;
        int kc = j >> 3, jj = j & 7;
        uint32_t off = (uint32_t)(row * 128 + jj * 16);
        uint32_t sw = off ^ ((off >> 3) & 0x70);
        *(uint4*)(dsm + PTR_A + kc * 4096 + sw) =
            *(const uint4*)(g_Gf16 + ((size_t)(b * 20 + row)) * 512 + kc * 64 + jj * 8);
    }

#define PLOADB(step)                                                          \
    do {                                                                      \
        int nt_ = (step) >> 3, kc_ = (step) & 7;                              \
        uint32_t st_ = sb + PTR_B + ((step) & 1) * 8192;                      \
        _Pragma("unroll")                                                     \
        for (int i_ = 0; i_ < 2; i_++) {                                      \
            int c_ = tid + i_ * 256;                                          \
            int row_ = c_ >> 3, j_ = c_ & 7;                                  \
            uint32_t off_ = row_ * 128 + j_ * 16;                             \
            uint32_t sw_ = off_ ^ ((off_ >> 3) & 0x70);                       \
            cp_async16(st_ + sw_,                                             \
                g_kvlh + ((size_t)b * 1000 + nsl * 512 + nt_ * 64 + row_) * 1536 + 1024 + kc_ * 64 + j_ * 8); \
        }                                                                     \
        cp_commit();                                                          \
    } while (0)

    PLOADB(0);
    __syncthreads();

    const int r0 = wm * 16 + (lane >> 2);
    const int r1 = r0 + 8;

    float acc[2][4];
    for (int step = 0; step < 64; ++step) {
        if (step + 1 < 64) { PLOADB(step + 1); cp_wait1(); } else { cp_wait0(); }
        __syncthreads();

        const int kc = step & 7;
        if (kc == 0) {
#pragma unroll
            for (int f = 0; f < 2; ++f)
#pragma unroll
                for (int r = 0; r < 4; ++r) acc[f][r] = 0.f;
        }

        uint32_t stB = sb + PTR_B + (step & 1) * 8192;
#pragma unroll
        for (int ks = 0; ks < 4; ++ks) {
            uint32_t a0, a1, a2, a3;
            uint32_t offA = (uint32_t)((wm * 16 + a_row) * 128 + ks * 32 + a_c16 * 16);
            ldsm_x4(a0, a1, a2, a3, sb + PTR_A + kc * 4096 + (offA ^ ((offA >> 3) & 0x70)));
            uint32_t offB = (uint32_t)((wn * 16 + b_nrow) * 128 + ks * 32 + b_c16 * 16);
            uint32_t bf0, bf1, bf2, bf3;
            ldsm_x4(bf0, bf1, bf2, bf3, stB + (offB ^ ((offB >> 3) & 0x70)));
            mma16816(acc[0][0], acc[0][1], acc[0][2], acc[0][3], a0, a1, a2, a3, bf0, bf1);
            mma16816(acc[1][0], acc[1][1], acc[1][2], acc[1][3], a0, a1, a2, a3, bf2, bf3);
        }

        if (kc == 7) {
            const int nt = step >> 3;
            const int nb = nsl * 512 + nt * 64 + wn * 16;
            const int widx = nb >> 5;
            unsigned int w0 = (r0 < 20) ? smask[r0 * 32 + widx] : 0u;
            unsigned int w1 = (r1 < 20) ? smask[r1 * 32 + widx] : 0u;
#pragma unroll
            for (int f = 0; f < 2; ++f) {
                int c = (lane & 3) * 2 + f * 8;
                int gn = nb + c;
                int bit = gn & 31;
                if (r0 < 20) {
                    if (gn < 1000) {
                        float lg = ((w0 >> bit) & 1u)
                                 ? 10.f * tanhf(acc[f][0] * INV_SQRT_D) : NEG_BIG;
                        g_logits[(size_t)(b * 20 + r0) * 1000 + gn] = lg;
                    }
                    if (gn + 1 < 1000) {
                        float lg = ((w0 >> (bit + 1)) & 1u)
                                 ? 10.f * tanhf(acc[f][1] * INV_SQRT_D) : NEG_BIG;
                        g_logits[(size_t)(b * 20 + r0) * 1000 + gn + 1] = lg;
                    }
                }
                if (r1 < 20) {
                    if (gn < 1000) {
                        float lg = ((w1 >> bit) & 1u)
                                 ? 10.f * tanhf(acc[f][2] * INV_SQRT_D) : NEG_BIG;
                        g_logits[(size_t)(b * 20 + r1) * 1000 + gn] = lg;
                    }
                    if (gn + 1 < 1000) {
                        float lg = ((w1 >> (bit + 1)) & 1u)
                                 ? 10.f * tanhf(acc[f][3] * INV_SQRT_D) : NEG_BIG;
                        g_logits[(size_t)(b * 20 + r1) * 1000 + gn + 1] = lg;
                    }
                }
            }
        }
        __syncthreads();
    }
#undef PLOADB
}

// ---------------- log-softmax + transposed writeout ----------------
__global__ __launch_bounds__(256)
void lsm_kernel(float* __restrict__ out)
{
    const int s = blockIdx.x, b = blockIdx.y;
    const float* row = g_logits + (size_t)(b * 20 + s) * 1000;
    float* orow = out + (size_t)(s * 64 + b) * 1000;
    __shared__ float red[8];
    const int tid = threadIdx.x;
    const int lane = tid & 31, w = tid >> 5;

    float mx = -1e30f;
    for (int i = tid; i < 1000; i += 256) mx = fmaxf(mx, row[i]);
    mx = warp_max(mx);
    if (lane == 0) red[w] = mx;
    __syncthreads();
    if (w == 0) {
        float v = (lane < 8) ? red[lane] : -1e30f;
        v = warp_max(v);
        if (lane == 0) red[0] = v;
    }
    __syncthreads();
    mx = red[0];
    __syncthreads();

    float se = 0.f;
    for (int i = tid; i < 1000; i += 256) se += __expf(row[i] - mx);
    se = warp_sum(se);
    if (lane == 0) red[w] = se;
    __syncthreads();
    if (w == 0) {
        float v = (lane < 8) ? red[lane] : 0.f;
        v = warp_sum(v);
        if (lane == 0) red[0] = v;
    }
    __syncthreads();
    const float lse = mx + logf(red[0]);

    for (int i = tid; i < 1000; i += 256) orow[i] = row[i] - lse;
}

// ---------------- launch ----------------
extern "C" void kernel_launch(void* const* d_in, const int* in_sizes, int n_in,
                              void* d_out, int out_size)
{
    (void)out_size;
    const float* emb = nullptr;
    const float* q = nullptr;
    const void* mask = nullptr;
    const float* Wkvl = nullptr;
    const float* Wout = nullptr;
    for (int i = 0; i < n_in; ++i) {
        switch (in_sizes[i]) {
            case 32768000: emb = (const float*)d_in[i]; break;
            case 655360:   q = (const float*)d_in[i]; break;
            case 1280000:  mask = d_in[i]; break;
            case 786432:   Wkvl = (const float*)d_in[i]; break;
            case 262144:   Wout = (const float*)d_in[i]; break;
            default: break;
        }
    }
    float* out = (float*)d_out;

    __half *kvlhp, *af16, *wkt, *wot, *hf16, *gf16;
    cudaGetSymbolAddress((void**)&kvlhp, g_kvlh);
    cudaGetSymbolAddress((void**)&af16, g_Af16);
    cudaGetSymbolAddress((void**)&wkt, g_Wkvl_t);
    cudaGetSymbolAddress((void**)&wot, g_Wout_t);
    cudaGetSymbolAddress((void**)&hf16, g_Hf16);
    cudaGetSymbolAddress((void**)&gf16, g_Gf16);

    cudaFuncSetAttribute(hmma_gemm128, cudaFuncAttributeMaxDynamicSharedMemorySize, 98304);
    cudaFuncSetAttribute(attn_mma_kernel, cudaFuncAttributeMaxDynamicSharedMemorySize, ATT_SMEM);
    cudaFuncSetAttribute(pointer_mma_kernel, cudaFuncAttributeMaxDynamicSharedMemorySize, PTR_SMEM);

    const unsigned int* mw = (const unsigned int*)mask;

    // 1: fused prep (emb fp16, W transposes, mask bits) — single launch
    prep_kernel<<<37376, 256>>>(emb, Wkvl, Wout, mw);

    // 2: kvl = embeddings @ W_kvl -> g_kvlh (2 CTAs/SM)
    {
        dim3 grid(12, 500);
        hmma_gemm128<<<grid, 256, 98304>>>(af16, wkt, kvlhp, 1536);
    }

    // 3: tensor-core attention
    {
        dim3 grid(8, 64);
        attn_mma_kernel<<<grid, 256, ATT_SMEM>>>(q);
    }

    // 4: glimpse = heads @ W_out -> fp16
    {
        dim3 grid(4, 10);
        hmma_gemm128<<<grid, 256, 98304>>>(hf16, wot, gf16, 512);
    }

    // 5: pointer logits via MMA
    {
        dim3 grid(2, 64);
        pointer_mma_kernel<<<grid, 256, PTR_SMEM>>>();
    }

    // 6: log-softmax
    {
        dim3 grid(20, 64);
        lsm_kernel<<<grid, 256>>>(out);
    }
}